// round 4
// baseline (speedup 1.0000x reference)
#include <cuda_runtime.h>
#include <math.h>

#define BB 2
#define SS 2048
#define EE 1024
#define HH 16
#define HD 64
#define MTOT (BB*SS)
#define SCALE 0.125f   // 1/sqrt(64)

// Scratch (allocation-free rule): device globals
__device__ float g_q[MTOT * EE];     // rounded Q proj
__device__ float g_k[MTOT * EE];
__device__ float g_v[MTOT * EE];
__device__ float g_att[MTOT * EE];   // rounded attention output
__device__ float g_xq[MTOT * EE];    // rounded inputs
__device__ float g_xk[MTOT * EE];
__device__ float g_xv[MTOT * EE];
__device__ float g_wq[EE * EE];      // rounded weights
__device__ float g_wk[EE * EE];
__device__ float g_wv[EE * EE];
__device__ float g_wo[EE * EE];

// ---------------------------------------------------------------------------
// helpers
// ---------------------------------------------------------------------------
__device__ __forceinline__ unsigned f2tf(float f) {
    unsigned r;
    asm("cvt.rna.tf32.f32 %0, %1;" : "=r"(r) : "f"(f));
    return r;
}

__device__ __forceinline__ void mma_tf32(float c[4], const unsigned a[4], const unsigned b[2]) {
    asm volatile(
        "mma.sync.aligned.m16n8k8.row.col.f32.tf32.tf32.f32 "
        "{%0,%1,%2,%3}, {%4,%5,%6,%7}, {%8,%9}, {%0,%1,%2,%3};"
        : "+f"(c[0]), "+f"(c[1]), "+f"(c[2]), "+f"(c[3])
        : "r"(a[0]), "r"(a[1]), "r"(a[2]), "r"(a[3]), "r"(b[0]), "r"(b[1]));
}

__device__ __forceinline__ void cpa16(unsigned dst, const void* src) {
    asm volatile("cp.async.cg.shared.global [%0], [%1], 16;" :: "r"(dst), "l"(src) : "memory");
}
__device__ __forceinline__ void cp_commit() { asm volatile("cp.async.commit_group;" ::: "memory"); }
__device__ __forceinline__ void cp_wait0() { asm volatile("cp.async.wait_group 0;" ::: "memory"); }
__device__ __forceinline__ void cp_wait1() { asm volatile("cp.async.wait_group 1;" ::: "memory"); }
__device__ __forceinline__ void cp_wait2() { asm volatile("cp.async.wait_group 2;" ::: "memory"); }

// ---------------------------------------------------------------------------
// Prepass: round 7 tensors to tf32 in-place-equivalent copies
// ---------------------------------------------------------------------------
struct RoundArgs {
    const float* src[7];
    float*       dst[7];
    int          n4[7];
};

__global__ __launch_bounds__(256) void tf32_round(RoundArgs a) {
    const int z = blockIdx.y;
    const int n4 = a.n4[z];
    const float4* s = (const float4*)a.src[z];
    float4* d = (float4*)a.dst[z];
    for (int i = blockIdx.x * blockDim.x + threadIdx.x; i < n4;
         i += gridDim.x * blockDim.x) {
        float4 v = s[i];
        v.x = __uint_as_float(f2tf(v.x));
        v.y = __uint_as_float(f2tf(v.y));
        v.z = __uint_as_float(f2tf(v.z));
        v.w = __uint_as_float(f2tf(v.w));
        d[i] = v;
    }
}

// ---------------------------------------------------------------------------
// GEMM: C[M,N] = A[M,K] @ W[N,K]^T + bias    (A, W pre-rounded to tf32)
// CTA 128x128x32, 512 threads (16 warps 4x4), warp tile 32x32.
// 3-stage cp.async smem pipeline. smem row stride 36 words (R2-proven layout).
// ---------------------------------------------------------------------------
#define GSTR 36
#define STG_W 9216   // words per stage: A 128*36 + B 128*36

struct QKVArgs {
    const float* A[3];
    const float* W[3];
    const float* bias[3];
    float*       C[3];
};

template<bool RND>
__device__ __forceinline__ void gemm_body(
    const float* __restrict__ A, const float* __restrict__ W,
    const float* __restrict__ bias, float* __restrict__ C)
{
    extern __shared__ float smf[];
    const unsigned smem_u = (unsigned)__cvta_generic_to_shared(smf);

    const int tid  = threadIdx.x;
    const int warp = tid >> 5, lane = tid & 31;
    const int g = lane >> 2, t = lane & 3;
    const int wm = warp & 3, wn = warp >> 2;
    const int bm = blockIdx.y * 128, bn = blockIdx.x * 128;

    // staging: thread handles A chunks {tid, tid+512}, B chunks {tid, tid+512}
    const int m0 = tid >> 3,          kq0 = tid & 7;
    const int m1 = (tid + 512) >> 3,  kq1 = (tid + 512) & 7;
    const float* As0 = A + (size_t)(bm + m0) * EE + kq0 * 4;
    const float* As1 = A + (size_t)(bm + m1) * EE + kq1 * 4;
    const float* Ws0 = W + (size_t)(bn + m0) * EE + kq0 * 4;
    const float* Ws1 = W + (size_t)(bn + m1) * EE + kq1 * 4;
    const unsigned dA0 = smem_u + (m0 * GSTR + kq0 * 4) * 4;
    const unsigned dA1 = smem_u + (m1 * GSTR + kq1 * 4) * 4;
    const unsigned dB0 = dA0 + 4608 * 4;
    const unsigned dB1 = dA1 + 4608 * 4;

    float acc[2][4][4] = {};

    const int NK = EE / 32;   // 32

    // prologue: stage tiles 0 and 1
    #pragma unroll
    for (int p = 0; p < 2; p++) {
        const unsigned so = p * STG_W * 4;
        cpa16(dA0 + so, As0 + p * 32);
        cpa16(dA1 + so, As1 + p * 32);
        cpa16(dB0 + so, Ws0 + p * 32);
        cpa16(dB1 + so, Ws1 + p * 32);
        cp_commit();
    }

    int st = 0;            // stage of tile kt
    for (int kt = 0; kt < NK; kt++) {
        if (kt + 2 < NK) {
            cp_wait1();
            __syncthreads();
            const int s2 = (st + 2 >= 3) ? st - 1 : st + 2;
            const unsigned so = s2 * STG_W * 4;
            const int ko = (kt + 2) * 32;
            cpa16(dA0 + so, As0 + ko);
            cpa16(dA1 + so, As1 + ko);
            cpa16(dB0 + so, Ws0 + ko);
            cpa16(dB1 + so, Ws1 + ko);
            cp_commit();
        } else {
            cp_wait0();
            __syncthreads();
        }

        const unsigned* Asm = (const unsigned*)smf + st * STG_W;
        const unsigned* Bsm = Asm + 4608;

        #pragma unroll
        for (int ksc = 0; ksc < 4; ksc++) {
            unsigned af[2][4], bf[4][2];
            #pragma unroll
            for (int mi = 0; mi < 2; mi++) {
                const int row = wm * 32 + mi * 16;
                af[mi][0] = Asm[(row + g)     * GSTR + ksc * 8 + t];
                af[mi][1] = Asm[(row + g + 8) * GSTR + ksc * 8 + t];
                af[mi][2] = Asm[(row + g)     * GSTR + ksc * 8 + t + 4];
                af[mi][3] = Asm[(row + g + 8) * GSTR + ksc * 8 + t + 4];
            }
            #pragma unroll
            for (int ni = 0; ni < 4; ni++) {
                const int col = wn * 32 + ni * 8 + g;
                bf[ni][0] = Bsm[col * GSTR + ksc * 8 + t];
                bf[ni][1] = Bsm[col * GSTR + ksc * 8 + t + 4];
            }
            #pragma unroll
            for (int mi = 0; mi < 2; mi++)
                #pragma unroll
                for (int ni = 0; ni < 4; ni++)
                    mma_tf32(acc[mi][ni], af[mi], bf[ni]);
        }
        st = (st + 1 >= 3) ? 0 : st + 1;
        __syncthreads();
    }

    // epilogue
    #pragma unroll
    for (int mi = 0; mi < 2; mi++) {
        #pragma unroll
        for (int r2 = 0; r2 < 2; r2++) {
            const int m = bm + wm * 32 + mi * 16 + g + r2 * 8;
            #pragma unroll
            for (int ni = 0; ni < 4; ni++) {
                const int n = bn + wn * 32 + ni * 8 + 2 * t;
                float2 bv = *(const float2*)(bias + n);
                float2 o;
                o.x = acc[mi][ni][r2 * 2 + 0] + bv.x;
                o.y = acc[mi][ni][r2 * 2 + 1] + bv.y;
                if (RND) {
                    o.x = __uint_as_float(f2tf(o.x));
                    o.y = __uint_as_float(f2tf(o.y));
                }
                *(float2*)(C + (size_t)m * EE + n) = o;
            }
        }
    }
}

__global__ __launch_bounds__(512, 1) void qkv_gemm(QKVArgs args) {
    const int z = blockIdx.z;
    gemm_body<true>(args.A[z], args.W[z], args.bias[z], args.C[z]);
}

__global__ __launch_bounds__(512, 1) void out_gemm(const float* __restrict__ A,
                                                   const float* __restrict__ W,
                                                   const float* __restrict__ bias,
                                                   float* __restrict__ C) {
    gemm_body<false>(A, W, bias, C);
}

// ---------------------------------------------------------------------------
// Flash attention (R2-proven layouts) + cp.async staging with K/V overlap.
// Block = (b, h, 64 q-rows), 128 threads (4 warps, 16 rows each).
// Ks/Vs: [kv_row][d], row stride 68 words. Pf: A-frag layout per warp.
// All g_q/g_k/g_v values are pre-rounded tf32 -> no cvt on stage.
// ---------------------------------------------------------------------------
#define ASTR 68

__global__ __launch_bounds__(128, 3) void attn_tc() {
    extern __shared__ unsigned sm[];
    unsigned* Kf = sm;                  // 64*68 = 4352 words
    unsigned* Vs = sm + 4352;           // 4352 words
    unsigned* Pf = sm + 8704;           // 4352 words (Q staging, then P)
    const unsigned smem_u = (unsigned)__cvta_generic_to_shared(sm);
    const unsigned Kf_u = smem_u, Vs_u = smem_u + 4352 * 4, Pf_u = smem_u + 8704 * 4;

    const int tid  = threadIdx.x;
    const int warp = tid >> 5, lane = tid & 31;
    const int g = lane >> 2, t = lane & 3;
    const int b = blockIdx.x >> 4, h = blockIdx.x & 15;
    const int q0 = blockIdx.y * 64;
    const size_t base = (size_t)b * SS * EE + (size_t)h * HD;

    // staging thread constants: 8 chunks per thread per 64x64 tile
    const int r0 = tid >> 4;         // 0..7, rows r0 + i*8
    const int c4 = tid & 15;         // 16B chunk within row
    const unsigned dstW = (r0 * ASTR + c4 * 4) * 4;   // byte offset of chunk (i=0)

    const float* qsrc = g_q + base + (size_t)(q0 + r0) * EE + c4 * 4;
    const float* ksrc = g_k + base + (size_t)r0 * EE + c4 * 4;
    const float* vsrc = g_v + base + (size_t)r0 * EE + c4 * 4;

    // ---- prologue: Q -> Pf, K0 -> Kf, V0 -> Vs
    #pragma unroll
    for (int i = 0; i < 8; i++)
        cpa16(Pf_u + dstW + i * 8 * ASTR * 4, qsrc + (size_t)i * 8 * EE);
    cp_commit();
    #pragma unroll
    for (int i = 0; i < 8; i++)
        cpa16(Kf_u + dstW + i * 8 * ASTR * 4, ksrc + (size_t)i * 8 * EE);
    cp_commit();
    #pragma unroll
    for (int i = 0; i < 8; i++)
        cpa16(Vs_u + dstW + i * 8 * ASTR * 4, vsrc + (size_t)i * 8 * EE);
    cp_commit();

    cp_wait2();          // Q ready; K0,V0 pending
    __syncthreads();

    // pull Q A-fragments, fold in SCALE (exact: power of two)
    unsigned qf[8][4];
    {
        const int row = warp * 16;
        #pragma unroll
        for (int ks = 0; ks < 8; ks++) {
            qf[ks][0] = Pf[(row + g)     * ASTR + ks * 8 + t];
            qf[ks][1] = Pf[(row + g + 8) * ASTR + ks * 8 + t];
            qf[ks][2] = Pf[(row + g)     * ASTR + ks * 8 + t + 4];
            qf[ks][3] = Pf[(row + g + 8) * ASTR + ks * 8 + t + 4];
            #pragma unroll
            for (int j = 0; j < 4; j++)
                qf[ks][j] = __float_as_uint(__uint_as_float(qf[ks][j]) * SCALE);
        }
    }

    float o[8][4] = {};
    float mrow0 = -1e30f, mrow1 = -1e30f, lrow0 = 0.f, lrow1 = 0.f;

    const int NT = SS / 64;
    for (int kt = 0; kt < NT; kt++) {
        // ---- K[kt] ready?  (pending: K[kt], V[kt])
        cp_wait1();
        __syncthreads();

        // ---- S = Q @ K^T
        float s[8][4] = {};
        #pragma unroll
        for (int ks = 0; ks < 8; ks++) {
            #pragma unroll
            for (int ni = 0; ni < 8; ni++) {
                unsigned bb[2];
                const int n = ni * 8 + g;
                bb[0] = Kf[n * ASTR + ks * 8 + t];
                bb[1] = Kf[n * ASTR + ks * 8 + t + 4];
                mma_tf32(s[ni], qf[ks], bb);
            }
        }

        // ---- online softmax (rows g, g+8; reduce across lanes t)
        float mx0 = -1e30f, mx1 = -1e30f;
        #pragma unroll
        for (int ni = 0; ni < 8; ni++) {
            mx0 = fmaxf(mx0, fmaxf(s[ni][0], s[ni][1]));
            mx1 = fmaxf(mx1, fmaxf(s[ni][2], s[ni][3]));
        }
        mx0 = fmaxf(mx0, __shfl_xor_sync(0xffffffffu, mx0, 1));
        mx0 = fmaxf(mx0, __shfl_xor_sync(0xffffffffu, mx0, 2));
        mx1 = fmaxf(mx1, __shfl_xor_sync(0xffffffffu, mx1, 1));
        mx1 = fmaxf(mx1, __shfl_xor_sync(0xffffffffu, mx1, 2));

        float mn0 = fmaxf(mrow0, mx0), mn1 = fmaxf(mrow1, mx1);
        float c0 = __expf(mrow0 - mn0), c1 = __expf(mrow1 - mn1);
        float sum0 = 0.f, sum1 = 0.f;
        #pragma unroll
        for (int ni = 0; ni < 8; ni++) {
            s[ni][0] = __expf(s[ni][0] - mn0);
            s[ni][1] = __expf(s[ni][1] - mn0);
            s[ni][2] = __expf(s[ni][2] - mn1);
            s[ni][3] = __expf(s[ni][3] - mn1);
            sum0 += s[ni][0] + s[ni][1];
            sum1 += s[ni][2] + s[ni][3];
        }
        sum0 += __shfl_xor_sync(0xffffffffu, sum0, 1);
        sum0 += __shfl_xor_sync(0xffffffffu, sum0, 2);
        sum1 += __shfl_xor_sync(0xffffffffu, sum1, 1);
        sum1 += __shfl_xor_sync(0xffffffffu, sum1, 2);
        lrow0 = lrow0 * c0 + sum0;  mrow0 = mn0;
        lrow1 = lrow1 * c1 + sum1;  mrow1 = mn1;
        #pragma unroll
        for (int ni = 0; ni < 8; ni++) {
            o[ni][0] *= c0; o[ni][1] *= c0;
            o[ni][2] *= c1; o[ni][3] *= c1;
        }

        // ---- Kf reads done; prefetch next K (overlaps PV phase)
        __syncthreads();
        if (kt + 1 < NT) {
            const float* kn = ksrc + (size_t)(kt + 1) * 64 * EE;
            #pragma unroll
            for (int i = 0; i < 8; i++)
                cpa16(Kf_u + dstW + i * 8 * ASTR * 4, kn + (size_t)i * 8 * EE);
            cp_commit();
            cp_wait1();   // V[kt] done (K[kt+1] still pending)
        } else {
            cp_wait0();
        }
        __syncthreads();

        // ---- write P (tf32) into warp-local Pf in A-frag layout
        {
            const int xg = (g >> 1) & 3;
            #pragma unroll
            for (int ni = 0; ni < 8; ni++) {
                unsigned x0 = f2tf(s[ni][0]), x1 = f2tf(s[ni][1]);
                unsigned x2 = f2tf(s[ni][2]), x3 = f2tf(s[ni][3]);
                unsigned bp = (warp * 8 + ni) * 128 + (t >> 1) * 2;
                *(uint2*)(Pf + bp + (g * 4 + (((2 * t)     & 3) ^ xg)) * 4) = make_uint2(x0, x2);
                *(uint2*)(Pf + bp + (g * 4 + (((2 * t + 1) & 3) ^ xg)) * 4) = make_uint2(x1, x3);
            }
        }
        __syncwarp();

        // ---- O += P @ V
        #pragma unroll
        for (int ks = 0; ks < 8; ks++) {
            uint4 av = *(const uint4*)(Pf + (warp * 8 + ks) * 128 +
                                       (g * 4 + (t ^ ((g >> 1) & 3))) * 4);
            unsigned af[4] = { av.x, av.y, av.z, av.w };
            #pragma unroll
            for (int ni = 0; ni < 8; ni++) {
                unsigned bb[2];
                const int n = ni * 8 + g;
                bb[0] = Vs[(ks * 8 + t)     * ASTR + n];
                bb[1] = Vs[(ks * 8 + t + 4) * ASTR + n];
                mma_tf32(o[ni], af, bb);
            }
        }
        __syncthreads();   // Vs reads done

        // ---- prefetch next V (overlaps next S phase)
        if (kt + 1 < NT) {
            const float* vn = vsrc + (size_t)(kt + 1) * 64 * EE;
            #pragma unroll
            for (int i = 0; i < 8; i++)
                cpa16(Vs_u + dstW + i * 8 * ASTR * 4, vn + (size_t)i * 8 * EE);
            cp_commit();
        }
    }

    // ---- normalize, round, store
    float inv0 = 1.f / lrow0, inv1 = 1.f / lrow1;
    const int r0q = q0 + warp * 16 + g;
    #pragma unroll
    for (int ni = 0; ni < 8; ni++) {
        const int d = h * HD + ni * 8 + 2 * t;
        float2 w0, w1;
        w0.x = __uint_as_float(f2tf(o[ni][0] * inv0));
        w0.y = __uint_as_float(f2tf(o[ni][1] * inv0));
        w1.x = __uint_as_float(f2tf(o[ni][2] * inv1));
        w1.y = __uint_as_float(f2tf(o[ni][3] * inv1));
        *(float2*)(g_att + (size_t)(b * SS + r0q)     * EE + d) = w0;
        *(float2*)(g_att + (size_t)(b * SS + r0q + 8) * EE + d) = w1;
    }
}

// ---------------------------------------------------------------------------
// Launch
// ---------------------------------------------------------------------------
extern "C" void kernel_launch(void* const* d_in, const int* in_sizes, int n_in,
                              void* d_out, int out_size)
{
    const float* query = (const float*)d_in[0];
    const float* key_  = (const float*)d_in[1];
    const float* value = (const float*)d_in[2];
    const float* Wq = (const float*)d_in[3];
    const float* bq = (const float*)d_in[4];
    const float* Wk = (const float*)d_in[5];
    const float* bk = (const float*)d_in[6];
    const float* Wv = (const float*)d_in[7];
    const float* bv = (const float*)d_in[8];
    const float* Wo = (const float*)d_in[9];
    const float* bo = (const float*)d_in[10];
    float* out = (float*)d_out;

    float *q, *k, *v, *att, *xq, *xk, *xv, *wq, *wk, *wv, *wo;
    cudaGetSymbolAddress((void**)&q,   g_q);
    cudaGetSymbolAddress((void**)&k,   g_k);
    cudaGetSymbolAddress((void**)&v,   g_v);
    cudaGetSymbolAddress((void**)&att, g_att);
    cudaGetSymbolAddress((void**)&xq,  g_xq);
    cudaGetSymbolAddress((void**)&xk,  g_xk);
    cudaGetSymbolAddress((void**)&xv,  g_xv);
    cudaGetSymbolAddress((void**)&wq,  g_wq);
    cudaGetSymbolAddress((void**)&wk,  g_wk);
    cudaGetSymbolAddress((void**)&wv,  g_wv);
    cudaGetSymbolAddress((void**)&wo,  g_wo);

    static bool attr_done = false;
    if (!attr_done) {
        cudaFuncSetAttribute(qkv_gemm, cudaFuncAttributeMaxDynamicSharedMemorySize, 3 * STG_W * 4);
        cudaFuncSetAttribute(out_gemm, cudaFuncAttributeMaxDynamicSharedMemorySize, 3 * STG_W * 4);
        cudaFuncSetAttribute(attn_tc,  cudaFuncAttributeMaxDynamicSharedMemorySize, 3 * 4352 * 4);
        attr_done = true;
    }

    // 1) prepass: round inputs + weights to tf32
    RoundArgs ra;
    ra.src[0] = query; ra.dst[0] = xq; ra.n4[0] = MTOT * EE / 4;
    ra.src[1] = key_;  ra.dst[1] = xk; ra.n4[1] = MTOT * EE / 4;
    ra.src[2] = value; ra.dst[2] = xv; ra.n4[2] = MTOT * EE / 4;
    ra.src[3] = Wq;    ra.dst[3] = wq; ra.n4[3] = EE * EE / 4;
    ra.src[4] = Wk;    ra.dst[4] = wk; ra.n4[4] = EE * EE / 4;
    ra.src[5] = Wv;    ra.dst[5] = wv; ra.n4[5] = EE * EE / 4;
    ra.src[6] = Wo;    ra.dst[6] = wo; ra.n4[6] = EE * EE / 4;
    tf32_round<<<dim3(1024, 7), 256>>>(ra);

    // 2) QKV projections
    QKVArgs args;
    args.A[0] = xq; args.A[1] = xk; args.A[2] = xv;
    args.W[0] = wq; args.W[1] = wk; args.W[2] = wv;
    args.bias[0] = bq; args.bias[1] = bk; args.bias[2] = bv;
    args.C[0] = q; args.C[1] = k; args.C[2] = v;
    qkv_gemm<<<dim3(EE / 128, MTOT / 128, 3), 512, 3 * STG_W * 4>>>(args);

    // 3) attention
    attn_tc<<<dim3(BB * HH, SS / 64), 128, 3 * 4352 * 4>>>();

    // 4) output projection
    out_gemm<<<dim3(EE / 128, MTOT / 128), 512, 3 * STG_W * 4>>>(att, Wo = wo, bo, out);
}